// round 15
// baseline (speedup 1.0000x reference)
#include <cuda_runtime.h>

// y[b,c] = b_fc[c] + dot(h[b,0,:], V[c,:]),  V = W_fc @ W_emb  ([2,768])
// (TreeLSTM scan in the reference is dead code; adj and recurrent weights unused.)
// B=32, N=128, FI=768, FO=128.
//
// Two nodes with Programmatic Dependent Launch. Evidence R13/R14: bench tracks
// A's CTA count (ramp/trigger/completion), not its instruction mix.
// R15: A shrunk to 12 CTAs x 512 threads (half of R7's 24).

#define B_  32
#define N_  128
#define FI_ 768
#define FO_ 128
#define NQ  (FI_/4)     // 192 f-quads

__device__ float4 g_V[2][NQ];   // scratch: V = W_fc @ W_emb (quad layout)

// ---- Kernel A: 12 blocks x 512 threads. Block owns 16 f-quads (64 f). ----
// Thread: og = t>>4 (one of 32 o-groups, 4 o's each), lq = t&15 (local quad).
__global__ __launch_bounds__(512, 1)
void rvnn_precompute_V(const float* __restrict__ W_emb,  // [FO,FI]
                       const float* __restrict__ W_fc)   // [2,FO]
{
    cudaTriggerProgrammaticLaunchCompletion();   // let B launch immediately

    const int t  = threadIdx.x;
    const int og = t >> 4;                  // 0..31 (4 o's each)
    const int lq = t & 15;                  // 0..15
    const int q  = (blockIdx.x << 4) + lq;  // global f-quad

    const float4* wemb4 = reinterpret_cast<const float4*>(W_emb);

    // Front-batch: 4 independent LDG.128 (16 lanes x 16B contiguous per o-row,
    // fully coalesced 256B) + broadcast W_fc scalars.
    float4 w[4];
    float  f0[4], f1[4];
    #pragma unroll
    for (int j = 0; j < 4; ++j) {
        const int o = og * 4 + j;
        w[j]  = __ldg(&wemb4[(size_t)o * NQ + q]);
        f0[j] = __ldg(&W_fc[o]);
        f1[j] = __ldg(&W_fc[FO_ + o]);
    }

    float4 a0 = make_float4(0.f, 0.f, 0.f, 0.f);
    float4 a1 = make_float4(0.f, 0.f, 0.f, 0.f);
    #pragma unroll
    for (int j = 0; j < 4; ++j) {
        a0.x = fmaf(f0[j], w[j].x, a0.x); a0.y = fmaf(f0[j], w[j].y, a0.y);
        a0.z = fmaf(f0[j], w[j].z, a0.z); a0.w = fmaf(f0[j], w[j].w, a0.w);
        a1.x = fmaf(f1[j], w[j].x, a1.x); a1.y = fmaf(f1[j], w[j].y, a1.y);
        a1.z = fmaf(f1[j], w[j].z, a1.z); a1.w = fmaf(f1[j], w[j].w, a1.w);
    }

    __shared__ float4 sp[32][2][16];        // [og][c][lq]
    sp[og][0][lq] = a0;
    sp[og][1][lq] = a1;
    __syncthreads();

    // 32 threads fold the 32 og-partials -> one V quad each.
    if (t < 32) {
        const int c = t >> 4, l = t & 15;
        float4 s = make_float4(0.f, 0.f, 0.f, 0.f);
        #pragma unroll
        for (int k = 0; k < 32; ++k) {
            float4 p = sp[k][c][l];
            s.x += p.x; s.y += p.y; s.z += p.z; s.w += p.w;
        }
        g_V[c][(blockIdx.x << 4) + l] = s;
    }
}

// ---- Kernel B: y[b,c] = b_fc[c] + dot(h[b,0,:], V[c,:]) ----
__global__ __launch_bounds__(192, 1)
void rvnn_head_kernel(const float* __restrict__ h,    // [B,N,FI]
                      const float* __restrict__ b_fc, // [2]
                      float* __restrict__ y)          // [B,2]
{
    const int b    = blockIdx.x;
    const int t    = threadIdx.x;           // 0..191
    const int warp = t >> 5;                // 0..5
    const int lane = t & 31;

    // h + bias loads issue while kernel A is still running (PDL overlap).
    const float4* hrow = reinterpret_cast<const float4*>(h + (size_t)b * N_ * FI_);
    float4 hv = __ldg(&hrow[t]);
    const float bf0 = __ldg(&b_fc[0]);
    const float bf1 = __ldg(&b_fc[1]);

    cudaGridDependencySynchronize();        // wait for A's g_V writes

    float4 v0 = g_V[0][t];
    float4 v1 = g_V[1][t];

    float a0 = fmaf(hv.x, v0.x, fmaf(hv.y, v0.y, fmaf(hv.z, v0.z, hv.w * v0.w)));
    float a1 = fmaf(hv.x, v1.x, fmaf(hv.y, v1.y, fmaf(hv.z, v1.z, hv.w * v1.w)));

    #pragma unroll
    for (int off = 16; off > 0; off >>= 1) {
        a0 += __shfl_down_sync(0xffffffffu, a0, off);
        a1 += __shfl_down_sync(0xffffffffu, a1, off);
    }

    __shared__ float w0[6], w1[6];
    if (lane == 0) { w0[warp] = a0; w1[warp] = a1; }
    __syncthreads();

    if (t == 0) {
        float s0 = w0[0] + w0[1] + w0[2] + w0[3] + w0[4] + w0[5];
        float s1 = w1[0] + w1[1] + w1[2] + w1[3] + w1[4] + w1[5];
        y[b * 2 + 0] = s0 + bf0;
        y[b * 2 + 1] = s1 + bf1;
    }
}

extern "C" void kernel_launch(void* const* d_in, const int* in_sizes, int n_in,
                              void* d_out, int out_size)
{
    // metadata order: h, adj, W_emb, W_ioux, b_ioux, W_iouh, b_iouh,
    //                 W_coux, b_coux, W_couh, b_couh, W_fc, b_fc
    const float* h     = (const float*)d_in[0];
    const float* W_emb = (const float*)d_in[2];
    const float* W_fc  = (const float*)d_in[11];
    const float* b_fc  = (const float*)d_in[12];
    float* y = (float*)d_out;

    rvnn_precompute_V<<<NQ / 16, 512>>>(W_emb, W_fc);   // 12 blocks

    cudaLaunchConfig_t cfg = {};
    cfg.gridDim  = dim3(B_, 1, 1);
    cfg.blockDim = dim3(192, 1, 1);
    cfg.dynamicSmemBytes = 0;
    cfg.stream = 0;
    cudaLaunchAttribute attrs[1];
    attrs[0].id = cudaLaunchAttributeProgrammaticStreamSerialization;
    attrs[0].val.programmaticStreamSerializationAllowed = 1;
    cfg.attrs = attrs;
    cfg.numAttrs = 1;
    cudaLaunchKernelEx(&cfg, rvnn_head_kernel, h, b_fc, y);
}

// round 16
// speedup vs baseline: 1.1071x; 1.1071x over previous
#include <cuda_runtime.h>

// y[b,c] = b_fc[c] + dot(h[b,0,:], V[c,:]),  V = W_fc @ W_emb  ([2,768])
// (TreeLSTM scan in the reference is dead code; adj and recurrent weights unused.)
// B=32, N=128, FI=768, FO=128.
//
// Two nodes with Programmatic Dependent Launch (R7 = best measured, 6.66us).
// R16: A byte-identical to R7 (24x256, scalar loads). B repacked: 8 CTAs x
// 768 threads, 4 batches per CTA (same per-batch 192-thread layout) -> 1/4
// the CTAs on the post-griddepsync tail.

#define B_  32
#define N_  128
#define FI_ 768
#define FO_ 128

__device__ float g_V[2][FI_];   // scratch: V = W_fc @ W_emb

// ---- Kernel A (exactly R7): V[c,f] = sum_o W_fc[c,o] * W_emb[o,f] ----
__global__ __launch_bounds__(256, 1)
void rvnn_precompute_V(const float* __restrict__ W_emb,  // [FO,FI]
                       const float* __restrict__ W_fc)   // [2,FO]
{
    cudaTriggerProgrammaticLaunchCompletion();

    const int t  = threadIdx.x;
    const int fl = t & 31;        // f within block
    const int g  = t >> 5;        // o-chunk 0..7
    const int f  = blockIdx.x * 32 + fl;

    float a0 = 0.0f, a1 = 0.0f;
    #pragma unroll
    for (int j = 0; j < 16; ++j) {
        const int o = g * 16 + j;
        float w = __ldg(&W_emb[(size_t)o * FI_ + f]);   // coalesced across lanes
        a0 = fmaf(__ldg(&W_fc[o]),       w, a0);
        a1 = fmaf(__ldg(&W_fc[FO_ + o]), w, a1);
    }

    __shared__ float sp0[8][32], sp1[8][32];
    sp0[g][fl] = a0;
    sp1[g][fl] = a1;
    __syncthreads();

    if (t < 32) {
        float s = 0.0f;
        #pragma unroll
        for (int k = 0; k < 8; ++k) s += sp0[k][t];
        g_V[0][blockIdx.x * 32 + t] = s;
    } else if (t < 64) {
        const int l = t - 32;
        float s = 0.0f;
        #pragma unroll
        for (int k = 0; k < 8; ++k) s += sp1[k][l];
        g_V[1][blockIdx.x * 32 + l] = s;
    }
}

// ---- Kernel B: 8 CTAs x 768 threads, 4 batches per CTA ----
__global__ __launch_bounds__(768, 1)
void rvnn_head_kernel(const float* __restrict__ h,    // [B,N,FI]
                      const float* __restrict__ b_fc, // [2]
                      float* __restrict__ y)          // [B,2]
{
    const int t    = threadIdx.x;            // 0..767
    const int sub  = t / 192;                // 0..3  (batch slot in this CTA)
    const int tt   = t - sub * 192;          // 0..191 (per-batch thread)
    const int b    = blockIdx.x * 4 + sub;   // batch
    const int warp = tt >> 5;                // 0..5 (warps never straddle subs)
    const int lane = t & 31;

    // h + bias loads issue while kernel A is still running (PDL overlap).
    const float4* hrow = reinterpret_cast<const float4*>(h + (size_t)b * N_ * FI_);
    float4 hv = __ldg(&hrow[tt]);
    const float bf0 = __ldg(&b_fc[0]);
    const float bf1 = __ldg(&b_fc[1]);

    cudaGridDependencySynchronize();         // wait for A's g_V writes

    float4 v0 = *reinterpret_cast<const float4*>(&g_V[0][tt * 4]);
    float4 v1 = *reinterpret_cast<const float4*>(&g_V[1][tt * 4]);

    float a0 = fmaf(hv.x, v0.x, fmaf(hv.y, v0.y, fmaf(hv.z, v0.z, hv.w * v0.w)));
    float a1 = fmaf(hv.x, v1.x, fmaf(hv.y, v1.y, fmaf(hv.z, v1.z, hv.w * v1.w)));

    #pragma unroll
    for (int off = 16; off > 0; off >>= 1) {
        a0 += __shfl_down_sync(0xffffffffu, a0, off);
        a1 += __shfl_down_sync(0xffffffffu, a1, off);
    }

    __shared__ float w0[4][6], w1[4][6];
    if (lane == 0) { w0[sub][warp] = a0; w1[sub][warp] = a1; }
    __syncthreads();

    if (tt == 0) {
        float s0 = w0[sub][0] + w0[sub][1] + w0[sub][2]
                 + w0[sub][3] + w0[sub][4] + w0[sub][5];
        float s1 = w1[sub][0] + w1[sub][1] + w1[sub][2]
                 + w1[sub][3] + w1[sub][4] + w1[sub][5];
        y[b * 2 + 0] = s0 + bf0;
        y[b * 2 + 1] = s1 + bf1;
    }
}

extern "C" void kernel_launch(void* const* d_in, const int* in_sizes, int n_in,
                              void* d_out, int out_size)
{
    // metadata order: h, adj, W_emb, W_ioux, b_ioux, W_iouh, b_iouh,
    //                 W_coux, b_coux, W_couh, b_couh, W_fc, b_fc
    const float* h     = (const float*)d_in[0];
    const float* W_emb = (const float*)d_in[2];
    const float* W_fc  = (const float*)d_in[11];
    const float* b_fc  = (const float*)d_in[12];
    float* y = (float*)d_out;

    rvnn_precompute_V<<<FI_ / 32, 256>>>(W_emb, W_fc);   // 24 blocks (R7)

    cudaLaunchConfig_t cfg = {};
    cfg.gridDim  = dim3(B_ / 4, 1, 1);    // 8 CTAs
    cfg.blockDim = dim3(768, 1, 1);
    cfg.dynamicSmemBytes = 0;
    cfg.stream = 0;
    cudaLaunchAttribute attrs[1];
    attrs[0].id = cudaLaunchAttributeProgrammaticStreamSerialization;
    attrs[0].val.programmaticStreamSerializationAllowed = 1;
    cfg.attrs = attrs;
    cfg.numAttrs = 1;
    cudaLaunchKernelEx(&cfg, rvnn_head_kernel, h, b_fc, y);
}